// round 1
// baseline (speedup 1.0000x reference)
#include <cuda_runtime.h>
#include <math.h>

#define NN 100000
#define EE 1250000
#define DD 64

// ---------------- scratch (device globals: no allocations allowed) ----------------
__device__ float    g_x   [NN*DD];        // current node features
__device__ float    g_xt  [NN*DD];        // xt / z scratch
__device__ float    g_h   [NN*DD];        // pre-norm h
__device__ float    g_tmp [NN*DD];        // gin hidden
__device__ float    g_xd  [NN*6*DD];      // x_dense [N,384]
__device__ int      g_cnt [NN];
__device__ int      g_fill[NN];
__device__ int      g_start[NN];
__device__ unsigned g_elist[EE];          // src | signbit<<31
__device__ int      g_bsum[1024];
__device__ double   g_csum[3*128];        // per pair: 64 sums + 64 sumsqs
__device__ float    g_gn  [256];          // mean, rsigma, gamma, beta (64 each)

__device__ __forceinline__ float gelu_f(float v) {
    return 0.5f * v * (1.0f + erff(v * 0.70710678118654752440f));
}

// ---------------- utility kernels ----------------
__global__ void zero_i_kernel(int* a, int n) {
    int i = blockIdx.x * blockDim.x + threadIdx.x;
    if (i < n) a[i] = 0;
}
__global__ void zero_d_kernel(double* a, int n) {
    int i = blockIdx.x * blockDim.x + threadIdx.x;
    if (i < n) a[i] = 0.0;
}

// ---------------- CSR build ----------------
__global__ void count_kernel(const int* __restrict__ ei, int* __restrict__ cnt) {
    int e = blockIdx.x * blockDim.x + threadIdx.x;
    if (e < EE) atomicAdd(&cnt[ei[e*3 + 1]], 1);
}

#define SCAN_BS 1024
__global__ void scan_block_kernel(const int* __restrict__ cnt, int* __restrict__ excl,
                                  int* __restrict__ bsum, int n) {
    __shared__ int s[SCAN_BS];
    int i = blockIdx.x * SCAN_BS + threadIdx.x;
    int v = (i < n) ? cnt[i] : 0;
    s[threadIdx.x] = v;
    __syncthreads();
    for (int off = 1; off < SCAN_BS; off <<= 1) {
        int t = (threadIdx.x >= off) ? s[threadIdx.x - off] : 0;
        __syncthreads();
        s[threadIdx.x] += t;
        __syncthreads();
    }
    if (i < n) excl[i] = s[threadIdx.x] - v;
    if (threadIdx.x == SCAN_BS - 1) bsum[blockIdx.x] = s[SCAN_BS - 1];
}
__global__ void scan_part_kernel(int* __restrict__ bs, int nb) {
    __shared__ int s[SCAN_BS];
    int v = (threadIdx.x < nb) ? bs[threadIdx.x] : 0;
    s[threadIdx.x] = v;
    __syncthreads();
    for (int off = 1; off < SCAN_BS; off <<= 1) {
        int t = (threadIdx.x >= off) ? s[threadIdx.x - off] : 0;
        __syncthreads();
        s[threadIdx.x] += t;
        __syncthreads();
    }
    if (threadIdx.x < nb) bs[threadIdx.x] = s[threadIdx.x] - v;
}
__global__ void scan_add_kernel(int* __restrict__ excl, const int* __restrict__ bs, int n) {
    int i = blockIdx.x * SCAN_BS + threadIdx.x;
    if (i < n) excl[i] += bs[blockIdx.x];
}
__global__ void fill_kernel(const int* __restrict__ ei, const int* __restrict__ start,
                            int* __restrict__ fill, unsigned* __restrict__ elist) {
    int e = blockIdx.x * blockDim.x + threadIdx.x;
    if (e >= EE) return;
    int src = ei[e*3 + 0];
    int dst = ei[e*3 + 1];
    int sg  = ei[e*3 + 2];
    int pos = start[dst] + atomicAdd(&fill[dst], 1);
    elist[pos] = (unsigned)src | (sg < 0 ? 0x80000000u : 0u);
}

// ---------------- GEMM: out[N,64] = in[N,Kdim] @ W[Kdim,64] + b ----------------
// block = 256 threads, tile = 64 rows. Per thread: 4 rows x 4 cols.
#define ROWACC(ACC, I)                                                              \
    { float4 xv = *(const float4*)(sX + (rgrp*4 + (I))*68 + k4*4);                  \
      ACC.x += xv.x*w0.x + xv.y*w1.x + xv.z*w2.x + xv.w*w3.x;                       \
      ACC.y += xv.x*w0.y + xv.y*w1.y + xv.z*w2.y + xv.w*w3.y;                       \
      ACC.z += xv.x*w0.z + xv.y*w1.z + xv.z*w2.z + xv.w*w3.z;                       \
      ACC.w += xv.x*w0.w + xv.y*w1.w + xv.z*w2.w + xv.w*w3.w; }

__global__ void gemm64_kernel(const float* __restrict__ in, int in_ld,
                              const float* __restrict__ W, const float* __restrict__ bias,
                              int Kdim,
                              float* __restrict__ out, int out_ld,
                              float* __restrict__ out2, int out2_ld,
                              int gelu_flag, int nrows)
{
    __shared__ float sW[64*64];
    __shared__ float sX[64*68];
    int t = threadIdx.x;
    int jgrp = t & 15, rgrp = t >> 4;
    int rowBase = blockIdx.x * 64;

    float4 bj = *(const float4*)(bias + jgrp*4);
    float4 acc0 = bj, acc1 = bj, acc2 = bj, acc3 = bj;

    for (int kc = 0; kc < Kdim; kc += 64) {
        const float4* Wg = (const float4*)(W + kc*64);
        float4* sW4 = (float4*)sW;
        sW4[t] = Wg[t]; sW4[t+256] = Wg[t+256]; sW4[t+512] = Wg[t+512]; sW4[t+768] = Wg[t+768];
#pragma unroll
        for (int q = 0; q < 4; q++) {
            int v = t + q*256;
            int r = v >> 4, c4 = v & 15;
            int gr = rowBase + r;
            float4 val = make_float4(0.f, 0.f, 0.f, 0.f);
            if (gr < nrows) val = *(const float4*)(in + (size_t)gr*in_ld + kc + c4*4);
            *(float4*)(sX + r*68 + c4*4) = val;
        }
        __syncthreads();
#pragma unroll
        for (int k4 = 0; k4 < 16; k4++) {
            float4 w0 = *(const float4*)(sW + (k4*4+0)*64 + jgrp*4);
            float4 w1 = *(const float4*)(sW + (k4*4+1)*64 + jgrp*4);
            float4 w2 = *(const float4*)(sW + (k4*4+2)*64 + jgrp*4);
            float4 w3 = *(const float4*)(sW + (k4*4+3)*64 + jgrp*4);
            ROWACC(acc0, 0) ROWACC(acc1, 1) ROWACC(acc2, 2) ROWACC(acc3, 3)
        }
        __syncthreads();
    }

    float4 accs[4] = {acc0, acc1, acc2, acc3};
#pragma unroll
    for (int i = 0; i < 4; i++) {
        int gr = rowBase + rgrp*4 + i;
        if (gr >= nrows) continue;
        float4 v = accs[i];
        if (gelu_flag) {
            v.x = gelu_f(v.x); v.y = gelu_f(v.y); v.z = gelu_f(v.z); v.w = gelu_f(v.w);
        }
        *(float4*)(out + (size_t)gr*out_ld + jgrp*4) = v;
        if (out2) *(float4*)(out2 + (size_t)gr*out2_ld + jgrp*4) = v;
    }
}

// ---------------- CSR gathers (atomic-free segment sums) ----------------
// h[n] = (sum_e sign_e * xt[src_e] + xt[n]) / deg[n] + x[n]
__global__ void sage_agg_kernel(const float* __restrict__ xt, const float* __restrict__ x,
                                const int* __restrict__ start, const int* __restrict__ cnt,
                                const unsigned* __restrict__ elist, float* __restrict__ h, int n)
{
    int w = (blockIdx.x * blockDim.x + threadIdx.x) >> 5;
    int lane = threadIdx.x & 31;
    if (w >= n) return;
    const float2* xt2 = (const float2*)xt;
    float2 acc = xt2[(size_t)w*32 + lane];
    int s0 = start[w], c = cnt[w];
    for (int e = 0; e < c; e++) {
        unsigned p = elist[s0 + e];
        int src = (int)(p & 0x7fffffffu);
        float2 v = xt2[(size_t)src*32 + lane];
        if (p & 0x80000000u) { acc.x -= v.x; acc.y -= v.y; }
        else                 { acc.x += v.x; acc.y += v.y; }
    }
    float invd = 1.0f / (float)(c + 1);
    float2 xv = ((const float2*)x)[(size_t)w*32 + lane];
    float2 o;
    o.x = acc.x * invd + xv.x;
    o.y = acc.y * invd + xv.y;
    ((float2*)h)[(size_t)w*32 + lane] = o;
}

// z[n] = x[n] + sum_e x[src_e]
__global__ void gin_agg_kernel(const float* __restrict__ x,
                               const int* __restrict__ start, const int* __restrict__ cnt,
                               const unsigned* __restrict__ elist, float* __restrict__ z, int n)
{
    int w = (blockIdx.x * blockDim.x + threadIdx.x) >> 5;
    int lane = threadIdx.x & 31;
    if (w >= n) return;
    const float2* x2 = (const float2*)x;
    float2 acc = x2[(size_t)w*32 + lane];
    int s0 = start[w], c = cnt[w];
    for (int e = 0; e < c; e++) {
        unsigned p = elist[s0 + e];
        int src = (int)(p & 0x7fffffffu);
        float2 v = x2[(size_t)src*32 + lane];
        acc.x += v.x; acc.y += v.y;
    }
    ((float2*)z)[(size_t)w*32 + lane] = acc;
}

// ---------------- graph-norm column stats ----------------
__global__ void colsum_kernel(const float* __restrict__ h, double* __restrict__ csum,
                              double* __restrict__ csumsq, int n)
{
    int f = threadIdx.x & 63, q = threadIdx.x >> 6;  // 256 threads: 4 row-lanes x 64 features
    float s = 0.f, s2 = 0.f;
    for (int r = blockIdx.x*4 + q; r < n; r += gridDim.x*4) {
        float v = h[(size_t)r*64 + f];
        s += v; s2 += v*v;
    }
    __shared__ float ss[256], ssq[256];
    ss[threadIdx.x] = s; ssq[threadIdx.x] = s2;
    __syncthreads();
    if (q == 0) {
        s  = ss[f]  + ss[64+f]  + ss[128+f]  + ss[192+f];
        s2 = ssq[f] + ssq[64+f] + ssq[128+f] + ssq[192+f];
        atomicAdd(&csum[f],   (double)s);
        atomicAdd(&csumsq[f], (double)s2);
    }
}

__global__ void gnfin_kernel(const double* __restrict__ csum, const double* __restrict__ csumsq,
                             const float* __restrict__ nw, const float* __restrict__ nb,
                             const float* __restrict__ rsw, const float* __restrict__ rsb,
                             const float* __restrict__ rbw, const float* __restrict__ rbb,
                             const float* __restrict__ rate_b, float* __restrict__ gn, int n)
{
    int f = threadIdx.x;  // 64 threads
    float rate = rate_b[0];
    double m   = csum[f] / (double)n;
    double var = csumsq[f] / (double)n - m*m;
    gn[f]       = (float)m;
    gn[64 + f]  = rsqrtf((float)var + 1e-5f);
    gn[128 + f] = nw[f] + (rsw[f]*rate + rsb[f]);
    gn[192 + f] = nb[f] + (rbw[f]*rate + rbb[f]);
}

__global__ void gnapply_kernel(const float* __restrict__ h, const float* __restrict__ gn,
                               float* __restrict__ x, float* __restrict__ xd, int n)
{
    int idx = blockIdx.x * blockDim.x + threadIdx.x;  // one per float2
    if (idx >= n*32) return;
    int j = idx & 31, r = idx >> 5;
    int f = j*2;
    float2 v = ((const float2*)h)[idx];
    float t0 = (v.x - gn[f])   * gn[64+f]   * gn[128+f]   + gn[192+f];
    float t1 = (v.y - gn[f+1]) * gn[64+f+1] * gn[128+f+1] + gn[192+f+1];
    float2 o = make_float2(gelu_f(t0), gelu_f(t1));
    ((float2*)x)[idx] = o;
    *(float2*)(xd + (size_t)r*384 + f) = o;
}

// ---------------- fused readout: warp per row ----------------
__global__ void readout_kernel(const float* __restrict__ xf,
                               const float* __restrict__ W1, const float* __restrict__ b1,
                               const float* __restrict__ g1, const float* __restrict__ be1,
                               const float* __restrict__ W2, const float* __restrict__ b2,
                               const float* __restrict__ g2, const float* __restrict__ be2,
                               const float* __restrict__ W3, const float* __restrict__ b3,
                               float* __restrict__ prob, int nrows)
{
    extern __shared__ float sm[];
    float* sW1 = sm;                 // 64*128
    float* sW2 = sm + 8192;          // 128*128
    float* sP  = sm + 8192 + 16384;  // b1,g1,be1,b2,g2,be2,W3 (7*128)
    int t = threadIdx.x;
    for (int v = t; v < 8192;  v += blockDim.x) sW1[v] = W1[v];
    for (int v = t; v < 16384; v += blockDim.x) sW2[v] = W2[v];
    if (t < 128) {
        sP[t]       = b1[t];  sP[128 + t] = g1[t];  sP[256 + t] = be1[t];
        sP[384 + t] = b2[t];  sP[512 + t] = g2[t];  sP[640 + t] = be2[t];
        sP[768 + t] = W3[t];
    }
    __syncthreads();

    int lane = t & 31, w = t >> 5;
    int nw = blockDim.x >> 5;
    float bias3 = b3[0];

    for (int row = blockIdx.x*nw + w; row < nrows; row += gridDim.x*nw) {
        float xa = xf[(size_t)row*64 + lane];
        float xb = xf[(size_t)row*64 + 32 + lane];

        // ---- layer 1: 64 -> 128 ----
        float4 a = *(const float4*)(sP + lane*4);
#pragma unroll
        for (int k = 0; k < 64; k++) {
            float xv = (k < 32) ? __shfl_sync(0xffffffffu, xa, k)
                                : __shfl_sync(0xffffffffu, xb, k - 32);
            float4 wv = *(const float4*)(sW1 + k*128 + lane*4);
            a.x += xv*wv.x; a.y += xv*wv.y; a.z += xv*wv.z; a.w += xv*wv.w;
        }
        // LN1 + relu
        {
            float s  = a.x + a.y + a.z + a.w;
            float s2 = a.x*a.x + a.y*a.y + a.z*a.z + a.w*a.w;
            for (int o = 16; o; o >>= 1) {
                s  += __shfl_xor_sync(0xffffffffu, s,  o);
                s2 += __shfl_xor_sync(0xffffffffu, s2, o);
            }
            float m   = s  * (1.0f/128.0f);
            float var = s2 * (1.0f/128.0f) - m*m;
            float rs  = rsqrtf(var + 1e-5f);
            float4 gg = *(const float4*)(sP + 128 + lane*4);
            float4 bb = *(const float4*)(sP + 256 + lane*4);
            a.x = fmaxf((a.x - m)*rs*gg.x + bb.x, 0.f);
            a.y = fmaxf((a.y - m)*rs*gg.y + bb.y, 0.f);
            a.z = fmaxf((a.z - m)*rs*gg.z + bb.z, 0.f);
            a.w = fmaxf((a.w - m)*rs*gg.w + bb.w, 0.f);
        }
        // ---- layer 2: 128 -> 128 ----
        float4 c = *(const float4*)(sP + 384 + lane*4);
#pragma unroll
        for (int k = 0; k < 128; k++) {
            int sl = k >> 2;
            float comp = ((k & 3) == 0) ? a.x : ((k & 3) == 1) ? a.y : ((k & 3) == 2) ? a.z : a.w;
            float hv = __shfl_sync(0xffffffffu, comp, sl);
            float4 wv = *(const float4*)(sW2 + k*128 + lane*4);
            c.x += hv*wv.x; c.y += hv*wv.y; c.z += hv*wv.z; c.w += hv*wv.w;
        }
        // LN2 + relu
        {
            float s  = c.x + c.y + c.z + c.w;
            float s2 = c.x*c.x + c.y*c.y + c.z*c.z + c.w*c.w;
            for (int o = 16; o; o >>= 1) {
                s  += __shfl_xor_sync(0xffffffffu, s,  o);
                s2 += __shfl_xor_sync(0xffffffffu, s2, o);
            }
            float m   = s  * (1.0f/128.0f);
            float var = s2 * (1.0f/128.0f) - m*m;
            float rs  = rsqrtf(var + 1e-5f);
            float4 gg = *(const float4*)(sP + 512 + lane*4);
            float4 bb = *(const float4*)(sP + 640 + lane*4);
            c.x = fmaxf((c.x - m)*rs*gg.x + bb.x, 0.f);
            c.y = fmaxf((c.y - m)*rs*gg.y + bb.y, 0.f);
            c.z = fmaxf((c.z - m)*rs*gg.z + bb.z, 0.f);
            c.w = fmaxf((c.w - m)*rs*gg.w + bb.w, 0.f);
        }
        // ---- layer 3: 128 -> 1, sigmoid ----
        float4 w3v = *(const float4*)(sP + 768 + lane*4);
        float p = c.x*w3v.x + c.y*w3v.y + c.z*w3v.z + c.w*w3v.w;
        for (int o = 16; o; o >>= 1) p += __shfl_xor_sync(0xffffffffu, p, o);
        if (lane == 0) prob[row] = 1.0f / (1.0f + expf(-(p + bias3)));
    }
}

// ---------------- host driver ----------------
extern "C" void kernel_launch(void* const* d_in, const int* in_sizes, int n_in,
                              void* d_out, int out_size)
{
    const float* init_emb    = (const float*)d_in[0];
    const int*   ei          = (const int*)  d_in[1];
    const float* rate_b      = (const float*)d_in[2];
    const float* sage_lin_W  = (const float*)d_in[3];
    const float* sage_lin_b  = (const float*)d_in[4];
    const float* sage_norm_w = (const float*)d_in[5];
    const float* sage_norm_b = (const float*)d_in[6];
    const float* sage_rs_w   = (const float*)d_in[7];
    const float* sage_rs_b   = (const float*)d_in[8];
    const float* sage_rb_w   = (const float*)d_in[9];
    const float* sage_rb_b   = (const float*)d_in[10];
    const float* gin_W1      = (const float*)d_in[11];
    const float* gin_b1      = (const float*)d_in[12];
    const float* gin_W2      = (const float*)d_in[13];
    const float* gin_b2      = (const float*)d_in[14];
    const float* fuse_W      = (const float*)d_in[15];
    const float* fuse_b      = (const float*)d_in[16];
    const float* ro_W1       = (const float*)d_in[17];
    const float* ro_b1       = (const float*)d_in[18];
    const float* ro_ln1_g    = (const float*)d_in[19];
    const float* ro_ln1_b    = (const float*)d_in[20];
    const float* ro_W2       = (const float*)d_in[21];
    const float* ro_b2       = (const float*)d_in[22];
    const float* ro_ln2_g    = (const float*)d_in[23];
    const float* ro_ln2_b    = (const float*)d_in[24];
    const float* ro_W3       = (const float*)d_in[25];
    const float* ro_b3       = (const float*)d_in[26];
    float* out = (float*)d_out;

    float *px, *pxt, *ph, *ptmp, *pxd, *pgn;
    int *pcnt, *pfill, *pstart, *pbsum;
    unsigned* pelist;
    double* pcsum;
    cudaGetSymbolAddress((void**)&px,    g_x);
    cudaGetSymbolAddress((void**)&pxt,   g_xt);
    cudaGetSymbolAddress((void**)&ph,    g_h);
    cudaGetSymbolAddress((void**)&ptmp,  g_tmp);
    cudaGetSymbolAddress((void**)&pxd,   g_xd);
    cudaGetSymbolAddress((void**)&pgn,   g_gn);
    cudaGetSymbolAddress((void**)&pcnt,  g_cnt);
    cudaGetSymbolAddress((void**)&pfill, g_fill);
    cudaGetSymbolAddress((void**)&pstart,g_start);
    cudaGetSymbolAddress((void**)&pbsum, g_bsum);
    cudaGetSymbolAddress((void**)&pelist,g_elist);
    cudaGetSymbolAddress((void**)&pcsum, g_csum);

    const int nblk  = (NN + SCAN_BS - 1) / SCAN_BS;     // 98
    const int egrid = (EE + 255) / 256;
    const int ggrid = (NN + 63) / 64;                   // 1563
    const int agrid = (NN + 7) / 8;                     // 12500 (warp per node)

    // ---- CSR build + stat-buffer zeroing (once per call) ----
    zero_i_kernel<<<(NN + 255)/256, 256>>>(pcnt, NN);
    zero_i_kernel<<<(NN + 255)/256, 256>>>(pfill, NN);
    zero_d_kernel<<<2, 256>>>(pcsum, 3*128);
    count_kernel<<<egrid, 256>>>(ei, pcnt);
    scan_block_kernel<<<nblk, SCAN_BS>>>(pcnt, pstart, pbsum, NN);
    scan_part_kernel<<<1, SCAN_BS>>>(pbsum, nblk);
    scan_add_kernel<<<nblk, SCAN_BS>>>(pstart, pbsum, NN);
    fill_kernel<<<egrid, 256>>>(ei, pstart, pfill, pelist);

    // ---- 3 SAGE+GIN pairs ----
    for (int i = 0; i < 3; i++) {
        const float* xin = (i == 0) ? init_emb : px;
        // xt = x @ Wsage + b
        gemm64_kernel<<<ggrid, 256>>>(xin, 64, sage_lin_W + i*4096, sage_lin_b + i*64, 64,
                                      pxt, 64, nullptr, 0, 0, NN);
        // h = (segsum(sign*xt[src]) + xt)/deg + x
        sage_agg_kernel<<<agrid, 256>>>(pxt, xin, pstart, pcnt, pelist, ph, NN);
        // graph-norm stats + params
        colsum_kernel<<<128, 256>>>(ph, pcsum + i*128, pcsum + i*128 + 64, NN);
        gnfin_kernel<<<1, 64>>>(pcsum + i*128, pcsum + i*128 + 64,
                                sage_norm_w + i*64, sage_norm_b + i*64,
                                sage_rs_w + i*64, sage_rs_b + i*64,
                                sage_rb_w + i*64, sage_rb_b + i*64,
                                rate_b, pgn, NN);
        // x = gelu(norm(h)); also write x_dense slice 2i
        gnapply_kernel<<<(NN*32 + 255)/256, 256>>>(ph, pgn, px, pxd + (size_t)(2*i)*64, NN);
        // z = x + segsum(x[src])
        gin_agg_kernel<<<agrid, 256>>>(px, pstart, pcnt, pelist, pxt, NN);
        // x = gelu(z@W1+b1) @ W2 + b2 ; write x_dense slice 2i+1
        gemm64_kernel<<<ggrid, 256>>>(pxt, 64, gin_W1 + i*4096, gin_b1 + i*64, 64,
                                      ptmp, 64, nullptr, 0, 1, NN);
        gemm64_kernel<<<ggrid, 256>>>(ptmp, 64, gin_W2 + i*4096, gin_b2 + i*64, 64,
                                      px, 64, pxd + (size_t)(2*i+1)*64, 384, 0, NN);
    }

    // ---- fuse: x_final = x_dense @ fuse_W + fuse_b -> out[0 : N*64) ----
    gemm64_kernel<<<ggrid, 256>>>(pxd, 384, fuse_W, fuse_b, 384,
                                  out, 64, nullptr, 0, 0, NN);

    // ---- fused readout -> prob at out[out_size - N : out_size) ----
    cudaFuncSetAttribute(readout_kernel, cudaFuncAttributeMaxDynamicSharedMemorySize, 102400);
    readout_kernel<<<592, 256, (8192 + 16384 + 7*128) * sizeof(float)>>>(
        out, ro_W1, ro_b1, ro_ln1_g, ro_ln1_b,
        ro_W2, ro_b2, ro_ln2_g, ro_ln2_b,
        ro_W3, ro_b3, out + (size_t)(out_size - NN), NN);
}